// round 1
// baseline (speedup 1.0000x reference)
#include <cuda_runtime.h>
#include <math.h>
#include <stdint.h>

#define N_LEVELS   16
#define HASH_SIZE  (1u << 19)
#define HASH_MASK  (HASH_SIZE - 1u)
#define BLOCK      256

struct Res16 { float r[N_LEVELS]; };

__device__ __forceinline__ float2 lerp2(float2 a, float2 b, float t) {
    float2 o;
    o.x = fmaf(t, b.x - a.x, a.x);
    o.y = fmaf(t, b.y - a.y, a.y);
    return o;
}

__global__ __launch_bounds__(BLOCK) void hash_encode_kernel(
    const float* __restrict__ xin,
    const float* __restrict__ tables,
    float* __restrict__ out,
    Res16 rp, int n)
{
    __shared__ float sxy[BLOCK * 3];

    const int base = blockIdx.x * BLOCK;
    // coalesced staging of this block's 256 points (3 floats each)
    #pragma unroll
    for (int j = threadIdx.x; j < BLOCK * 3; j += BLOCK) {
        int g = base * 3 + j;
        sxy[j] = (g < n * 3) ? xin[g] : 0.0f;
    }
    __syncthreads();

    const int i = base + threadIdx.x;
    if (i >= n) return;

    const float px = sxy[threadIdx.x * 3 + 0];
    const float py = sxy[threadIdx.x * 3 + 1];
    const float pz = sxy[threadIdx.x * 3 + 2];

    float acc[2 * N_LEVELS];

    #pragma unroll
    for (int L = 0; L < N_LEVELS; ++L) {
        const float res = rp.r[L];
        const float sx = px * res;
        const float sy = py * res;
        const float sz = pz * res;
        const int ix = (int)sx;          // trunc == floor for x >= 0, matches ref
        const int iy = (int)sy;
        const int iz = (int)sz;
        const float fx = sx - (float)ix;
        const float fy = sy - (float)iy;
        const float fz = sz - (float)iz;

        // hash: (x*1) ^ (y*2654435761) ^ (z*805459861), uint32 wrap, masked
        const unsigned ux0 = (unsigned)ix;
        const unsigned ux1 = ux0 + 1u;
        const unsigned hy0 = (unsigned)iy * 2654435761u;
        const unsigned hy1 = hy0 + 2654435761u;
        const unsigned hz0 = (unsigned)iz * 805459861u;
        const unsigned hz1 = hz0 + 805459861u;

        const unsigned c00 = ux0 ^ hy0;
        const unsigned c10 = ux1 ^ hy0;
        const unsigned c01 = ux0 ^ hy1;
        const unsigned c11 = ux1 ^ hy1;

        const float2* __restrict__ tab =
            reinterpret_cast<const float2*>(tables) + (size_t)L * HASH_SIZE;

        // 8 independent gathers (one LOP3 each for (c ^ hz) & mask)
        const float2 f000 = __ldg(tab + ((c00 ^ hz0) & HASH_MASK));
        const float2 f100 = __ldg(tab + ((c10 ^ hz0) & HASH_MASK));
        const float2 f010 = __ldg(tab + ((c01 ^ hz0) & HASH_MASK));
        const float2 f110 = __ldg(tab + ((c11 ^ hz0) & HASH_MASK));
        const float2 f001 = __ldg(tab + ((c00 ^ hz1) & HASH_MASK));
        const float2 f101 = __ldg(tab + ((c10 ^ hz1) & HASH_MASK));
        const float2 f011 = __ldg(tab + ((c01 ^ hz1) & HASH_MASK));
        const float2 f111 = __ldg(tab + ((c11 ^ hz1) & HASH_MASK));

        // trilinear via lerp tree (x, then y, then z)
        const float2 v00 = lerp2(f000, f100, fx);
        const float2 v10 = lerp2(f010, f110, fx);
        const float2 v01 = lerp2(f001, f101, fx);
        const float2 v11 = lerp2(f011, f111, fx);
        const float2 w0  = lerp2(v00, v10, fy);
        const float2 w1  = lerp2(v01, v11, fy);
        const float2 rr  = lerp2(w0, w1, fz);

        acc[2 * L + 0] = rr.x;
        acc[2 * L + 1] = rr.y;
    }

    // level-major concat: out[i, 2L + f]; write as 8 x float4 (128B aligned)
    float4* o4 = reinterpret_cast<float4*>(out + (size_t)i * (2 * N_LEVELS));
    #pragma unroll
    for (int k = 0; k < 8; ++k) {
        float4 v;
        v.x = acc[4 * k + 0];
        v.y = acc[4 * k + 1];
        v.z = acc[4 * k + 2];
        v.w = acc[4 * k + 3];
        o4[k] = v;
    }
}

extern "C" void kernel_launch(void* const* d_in, const int* in_sizes, int n_in,
                              void* d_out, int out_size) {
    const float* x      = (const float*)d_in[0];
    const float* tables = (const float*)d_in[1];
    float* out          = (float*)d_out;

    const int n = in_sizes[0] / 3;

    // Replicate the reference's resolution computation bit-for-bit:
    // growth = (512/16) ** (1/15) in double (libm pow, same as CPython),
    // res_i = float(int(16.0 * growth**i))
    Res16 rp;
    const double growth = pow(512.0 / 16.0, 1.0 / (double)(N_LEVELS - 1));
    for (int l = 0; l < N_LEVELS; ++l) {
        double r = 16.0 * pow(growth, (double)l);
        rp.r[l] = (float)(long long)r;   // trunc toward zero, like Python int()
    }

    const int blocks = (n + BLOCK - 1) / BLOCK;
    hash_encode_kernel<<<blocks, BLOCK>>>(x, tables, out, rp, n);
}